// round 4
// baseline (speedup 1.0000x reference)
#include <cuda_runtime.h>
#include <math.h>

// ---------------- problem constants ----------------
#define D_DIM 2048
#define M_DIM 7168
#define E_NUM 8
#define T_TOK 4096            // B*S
#define TR    (T_TOK * 2)     // top-2 replicas

#define BM 64
#define BN 64
#define BK 16
#define CHUNK_M 1024                    // M processed in 7 chunks
#define N_CHUNKS (M_DIM / CHUNK_M)      // 7
#define MAX_TILES 160
#define MAX_RT    136                   // max row tiles = 8192/64 + 8
#define MAX_ROWS  (TR + E_NUM * BM)     // 8704 padded permuted rows

// ---------------- static device scratch (no allocs allowed) ----------------
__device__ float g_hc[(size_t)MAX_ROWS * CHUNK_M];  // gated hidden, one M-chunk (35.7 MB)
__device__ float g_outrep[(size_t)TR * D_DIM];      // per-replica expert output (67 MB)
__device__ int   g_row_map[MAX_ROWS];               // permuted row -> source token (or -1 pad)
__device__ int   g_repl_map[MAX_ROWS];              // permuted row -> replica id (or -1 pad)
__device__ int   g_eidx[TR];                        // replica -> expert
__device__ float g_tw[TR];                          // replica -> combine weight
__device__ int   g_tile_e[MAX_TILES];
__device__ int   g_tile_row[MAX_TILES];
__device__ int   g_ntiles;

// ---------------- init ----------------
__global__ void k_init() {
    for (int i = threadIdx.x; i < MAX_ROWS; i += blockDim.x) {
        g_row_map[i]  = -1;
        g_repl_map[i] = -1;
    }
}

// ---------------- router: one warp per token ----------------
__global__ void k_router(const float* __restrict__ x, const float* __restrict__ gw) {
    int warp = (blockIdx.x * blockDim.x + threadIdx.x) >> 5;
    int lane = threadIdx.x & 31;
    if (warp >= T_TOK) return;
    const float* xr = x + (size_t)warp * D_DIM;

    float acc[8] = {0.f,0.f,0.f,0.f,0.f,0.f,0.f,0.f};
    for (int k = lane; k < D_DIM; k += 32) {
        float xv = xr[k];
        const float4* g4 = (const float4*)(gw + (size_t)k * E_NUM);
        float4 g0 = g4[0];
        float4 g1 = g4[1];
        acc[0] += xv * g0.x; acc[1] += xv * g0.y;
        acc[2] += xv * g0.z; acc[3] += xv * g0.w;
        acc[4] += xv * g1.x; acc[5] += xv * g1.y;
        acc[6] += xv * g1.z; acc[7] += xv * g1.w;
    }
#pragma unroll
    for (int e = 0; e < 8; e++) {
#pragma unroll
        for (int o = 16; o > 0; o >>= 1)
            acc[e] += __shfl_xor_sync(0xFFFFFFFFu, acc[e], o);
    }
    if (lane == 0) {
        int e0 = 0; float l0 = acc[0];
#pragma unroll
        for (int e = 1; e < 8; e++)
            if (acc[e] > l0) { l0 = acc[e]; e0 = e; }
        int e1 = -1; float l1 = -3.4e38f;
#pragma unroll
        for (int e = 0; e < 8; e++)
            if (e != e0 && acc[e] > l1) { l1 = acc[e]; e1 = e; }
        // normalized pair weights from softmax over the two logits
        float w0 = 1.f / (1.f + __expf(l1 - l0));
        float w1 = 1.f - w0;
        g_eidx[2 * warp]     = e0;
        g_eidx[2 * warp + 1] = e1;
        g_tw[2 * warp]       = w0;
        g_tw[2 * warp + 1]   = w1;
    }
}

// ---------------- permutation + tile list (single block) ----------------
__global__ void k_perm() {
    __shared__ int sc[E_NUM];
    __shared__ int soff[E_NUM];
    __shared__ int scur[E_NUM];
    int t = threadIdx.x;
    if (t < E_NUM) { sc[t] = 0; scur[t] = 0; }
    __syncthreads();
    for (int r = t; r < TR; r += blockDim.x)
        atomicAdd(&sc[g_eidx[r]], 1);
    __syncthreads();
    if (t == 0) {
        int off = 0, nt = 0;
        for (int e = 0; e < E_NUM; e++) {
            soff[e] = off;
            int cnt = sc[e];
            for (int t0 = 0; t0 < cnt; t0 += BM) {
                g_tile_e[nt]   = e;
                g_tile_row[nt] = off + t0;
                nt++;
            }
            off += ((cnt + BM - 1) / BM) * BM;
        }
        g_ntiles = nt;
    }
    __syncthreads();
    for (int r = t; r < TR; r += blockDim.x) {
        int e   = g_eidx[r];
        int pos = soff[e] + atomicAdd(&scur[e], 1);
        g_row_map[pos]  = r >> 1;   // token
        g_repl_map[pos] = r;        // replica
    }
}

// -------- GEMM1 (chunked): g_hc = silu(X@W1[:,c0:c0+CHUNK]) * (X@W3[:,c0:...]) --------
__global__ void __launch_bounds__(256)
k_gemm1(const float* __restrict__ x,
        const float* __restrict__ w1,
        const float* __restrict__ w3,
        int c0) {
    int bx = blockIdx.x;
    if (bx >= g_ntiles) return;
    int e  = g_tile_e[bx];
    int r0 = g_tile_row[bx];
    int nl = blockIdx.y * BN;        // local column within chunk
    int n0 = c0 + nl;                // global column in W1/W3

    const float* W1 = w1 + (size_t)e * D_DIM * M_DIM;
    const float* W3 = w3 + (size_t)e * D_DIM * M_DIM;

    __shared__ float As[BK][BM];
    __shared__ float B1s[BK][BN];
    __shared__ float B3s[BK][BN];

    int tid = threadIdx.x;
    int tx = tid & 15, ty = tid >> 4;

    int arow = tid >> 2;            // 0..63
    int ak   = (tid & 3) * 4;       // 0,4,8,12
    int brow = tid >> 4;            // 0..15
    int bj   = (tid & 15) * 4;      // 0..60

    int grow = g_row_map[r0 + arow];
    const float* ap = (grow >= 0) ? (x + (size_t)grow * D_DIM) : x;

    float acc1[4][4] = {{0}}, acc3[4][4] = {{0}};

    // prologue: prefetch tile 0 into registers
    float4 av = make_float4(0.f, 0.f, 0.f, 0.f);
    if (grow >= 0) av = *(const float4*)(ap + ak);
    float4 b1v = *(const float4*)(W1 + (size_t)brow * M_DIM + n0 + bj);
    float4 b3v = *(const float4*)(W3 + (size_t)brow * M_DIM + n0 + bj);

    for (int k0 = 0; k0 < D_DIM; k0 += BK) {
        As[ak + 0][arow] = av.x;
        As[ak + 1][arow] = av.y;
        As[ak + 2][arow] = av.z;
        As[ak + 3][arow] = av.w;
        *(float4*)&B1s[brow][bj] = b1v;
        *(float4*)&B3s[brow][bj] = b3v;
        __syncthreads();

        int k1 = k0 + BK;
        if (k1 < D_DIM) {
            av = make_float4(0.f, 0.f, 0.f, 0.f);
            if (grow >= 0) av = *(const float4*)(ap + k1 + ak);
            b1v = *(const float4*)(W1 + (size_t)(k1 + brow) * M_DIM + n0 + bj);
            b3v = *(const float4*)(W3 + (size_t)(k1 + brow) * M_DIM + n0 + bj);
        }

#pragma unroll
        for (int kk = 0; kk < BK; kk++) {
            float4 a  = *(const float4*)&As[kk][ty * 4];
            float4 b1 = *(const float4*)&B1s[kk][tx * 4];
            float4 b3 = *(const float4*)&B3s[kk][tx * 4];
            float aa[4]  = {a.x, a.y, a.z, a.w};
            float bb1[4] = {b1.x, b1.y, b1.z, b1.w};
            float bb3[4] = {b3.x, b3.y, b3.z, b3.w};
#pragma unroll
            for (int i = 0; i < 4; i++)
#pragma unroll
                for (int j = 0; j < 4; j++) {
                    acc1[i][j] += aa[i] * bb1[j];
                    acc3[i][j] += aa[i] * bb3[j];
                }
        }
        __syncthreads();
    }

#pragma unroll
    for (int i = 0; i < 4; i++) {
        int row = r0 + ty * 4 + i;
        if (g_row_map[row] < 0) continue;
        float* hp = g_hc + (size_t)row * CHUNK_M + nl + tx * 4;
        float4 o;
        float v;
        v = acc1[i][0]; o.x = (v / (1.f + __expf(-v))) * acc3[i][0];
        v = acc1[i][1]; o.y = (v / (1.f + __expf(-v))) * acc3[i][1];
        v = acc1[i][2]; o.z = (v / (1.f + __expf(-v))) * acc3[i][2];
        v = acc1[i][3]; o.w = (v / (1.f + __expf(-v))) * acc3[i][3];
        *(float4*)hp = o;
    }
}

// -------- GEMM2 (chunked): out_rep (+)= g_hc @ W2[c0:c0+CHUNK, :], scatter by replica ----
__global__ void __launch_bounds__(256)
k_gemm2(const float* __restrict__ w2, int c0, int first) {
    int bx = blockIdx.x;
    if (bx >= g_ntiles) return;
    int e  = g_tile_e[bx];
    int r0 = g_tile_row[bx];
    int n0 = blockIdx.y * BN;

    const float* W2 = w2 + (size_t)e * M_DIM * D_DIM + (size_t)c0 * D_DIM;

    __shared__ float As[BK][BM];
    __shared__ float Bs[BK][BN];

    int tid = threadIdx.x;
    int tx = tid & 15, ty = tid >> 4;

    int arow = tid >> 2;
    int ak   = (tid & 3) * 4;
    int brow = tid >> 4;
    int bj   = (tid & 15) * 4;

    const float* ap = g_hc + (size_t)(r0 + arow) * CHUNK_M;

    float acc[4][4] = {{0}};

    // prologue: prefetch tile 0
    float4 av = *(const float4*)(ap + ak);
    float4 bv = *(const float4*)(W2 + (size_t)brow * D_DIM + n0 + bj);

    for (int k0 = 0; k0 < CHUNK_M; k0 += BK) {
        As[ak + 0][arow] = av.x;
        As[ak + 1][arow] = av.y;
        As[ak + 2][arow] = av.z;
        As[ak + 3][arow] = av.w;
        *(float4*)&Bs[brow][bj] = bv;
        __syncthreads();

        int k1 = k0 + BK;
        if (k1 < CHUNK_M) {
            av = *(const float4*)(ap + k1 + ak);
            bv = *(const float4*)(W2 + (size_t)(k1 + brow) * D_DIM + n0 + bj);
        }

#pragma unroll
        for (int kk = 0; kk < BK; kk++) {
            float4 a = *(const float4*)&As[kk][ty * 4];
            float4 b = *(const float4*)&Bs[kk][tx * 4];
            float aa[4] = {a.x, a.y, a.z, a.w};
            float bb[4] = {b.x, b.y, b.z, b.w};
#pragma unroll
            for (int i = 0; i < 4; i++)
#pragma unroll
                for (int j = 0; j < 4; j++)
                    acc[i][j] += aa[i] * bb[j];
        }
        __syncthreads();
    }

#pragma unroll
    for (int i = 0; i < 4; i++) {
        int row = r0 + ty * 4 + i;
        int rr  = g_repl_map[row];
        if (rr < 0) continue;
        float* op = g_outrep + (size_t)rr * D_DIM + n0 + tx * 4;
        float4 o = make_float4(acc[i][0], acc[i][1], acc[i][2], acc[i][3]);
        if (!first) {
            float4 p = *(const float4*)op;
            o.x += p.x; o.y += p.y; o.z += p.z; o.w += p.w;
        }
        *(float4*)op = o;
    }
}

// ---------------- combine: out[t] = w0*rep[2t] + w1*rep[2t+1] ----------------
__global__ void k_combine(float* __restrict__ out) {
    int i = blockIdx.x * blockDim.x + threadIdx.x;   // float4 index
    int t = i >> 9;                                  // 512 float4 per row
    int c = (i & 511) * 4;
    if (t >= T_TOK) return;
    float w0 = g_tw[2 * t];
    float w1 = g_tw[2 * t + 1];
    float4 a = *(const float4*)&g_outrep[(size_t)(2 * t) * D_DIM + c];
    float4 b = *(const float4*)&g_outrep[(size_t)(2 * t + 1) * D_DIM + c];
    float4 o;
    o.x = w0 * a.x + w1 * b.x;
    o.y = w0 * a.y + w1 * b.y;
    o.z = w0 * a.z + w1 * b.z;
    o.w = w0 * a.w + w1 * b.w;
    *(float4*)&out[(size_t)t * D_DIM + c] = o;
}

// ---------------- launch ----------------
extern "C" void kernel_launch(void* const* d_in, const int* in_sizes, int n_in,
                              void* d_out, int out_size) {
    const float* x  = (const float*)d_in[0];
    const float* gw = (const float*)d_in[1];
    const float* w1 = (const float*)d_in[2];
    const float* w2 = (const float*)d_in[3];
    const float* w3 = (const float*)d_in[4];
    float* out = (float*)d_out;

    k_init<<<1, 256>>>();
    k_router<<<T_TOK / 8, 256>>>(x, gw);
    k_perm<<<1, 256>>>();
    for (int c = 0; c < N_CHUNKS; c++) {
        int c0 = c * CHUNK_M;
        k_gemm1<<<dim3(MAX_RT, CHUNK_M / BN), 256>>>(x, w1, w3, c0);
        k_gemm2<<<dim3(MAX_RT, D_DIM / BN), 256>>>(w2, c0, c == 0);
    }
    k_combine<<<(T_TOK * D_DIM / 4) / 256, 256>>>(out);
}